// round 1
// baseline (speedup 1.0000x reference)
#include <cuda_runtime.h>

// Problem dims (fixed by the dataset): x (B, K), mu (K, U), out (B, U)
#define B_DIM 8192
#define K_DIM 1024
#define N_DIM 4096

// GEMM tiling
#define BM 128
#define BN 128
#define BK 16
#define TM 8
#define TN 8
#define APAD 4   // pad As rows to kill STS bank conflicts, keep 16B alignment

// Scratch for row/col squared norms (no allocations allowed -> device globals)
__device__ float g_xsq[B_DIM];
__device__ float g_musq[N_DIM];

// ---------------------------------------------------------------------------
// ||x_row||^2 : one block per row, 256 threads, warp+block reduce
// ---------------------------------------------------------------------------
__global__ __launch_bounds__(256) void xsq_kernel(const float* __restrict__ x) {
    int row = blockIdx.x;
    const float4* xr = (const float4*)(x + (size_t)row * K_DIM);
    float s = 0.f;
    for (int i = threadIdx.x; i < K_DIM / 4; i += 256) {
        float4 v = xr[i];
        s += v.x * v.x + v.y * v.y + v.z * v.z + v.w * v.w;
    }
    __shared__ float sm[8];
    #pragma unroll
    for (int o = 16; o > 0; o >>= 1) s += __shfl_xor_sync(0xffffffffu, s, o);
    if ((threadIdx.x & 31) == 0) sm[threadIdx.x >> 5] = s;
    __syncthreads();
    if (threadIdx.x < 32) {
        s = (threadIdx.x < 8) ? sm[threadIdx.x] : 0.f;
        #pragma unroll
        for (int o = 4; o > 0; o >>= 1) s += __shfl_xor_sync(0xffffffffu, s, o);
        if (threadIdx.x == 0) g_xsq[row] = s;
    }
}

// ---------------------------------------------------------------------------
// ||mu_col||^2 : one thread per column, coalesced across K
// ---------------------------------------------------------------------------
__global__ __launch_bounds__(256) void musq_kernel(const float* __restrict__ mu) {
    int n = blockIdx.x * 256 + threadIdx.x;
    if (n >= N_DIM) return;
    float s = 0.f;
    #pragma unroll 4
    for (int k = 0; k < K_DIM; k++) {
        float v = mu[(size_t)k * N_DIM + n];
        s += v * v;
    }
    g_musq[n] = s;
}

// ---------------------------------------------------------------------------
// Fused GEMM + RBF epilogue:
//   out[m][n] = exp(-gamma * (xsq[m] + musq[n] - 2 * (x @ mu)[m][n]))
// 128x128 block tile, 8x8 per-thread microtile, BK=16.
// ---------------------------------------------------------------------------
__global__ __launch_bounds__(256) void rbf_gemm_kernel(
    const float* __restrict__ x,
    const float* __restrict__ mu,
    const float* __restrict__ gamma_p,
    float* __restrict__ out)
{
    __shared__ float As[BK][BM + APAD];  // A transposed: As[k][m]
    __shared__ float Bs[BK][BN];         // Bs[k][n]

    const int tid = threadIdx.x;
    const int block_m = blockIdx.y * BM;
    const int block_n = blockIdx.x * BN;

    // A-tile load map: 128 rows x 16 cols, float4 per load, 2 loads/thread
    const int aRow = tid >> 2;           // 0..63
    const int aCol = (tid & 3) * 4;      // 0,4,8,12
    // B-tile load map: 16 rows x 128 cols, float4 per load, 2 loads/thread
    const int bRow = tid >> 5;           // 0..7
    const int bCol = (tid & 31) * 4;     // 0..124

    // compute map
    const int ty = tid >> 4;             // 0..15 -> 8 rows each
    const int tx = tid & 15;             // 0..15 -> 8 cols each

    const float* xg = x + (size_t)(block_m + aRow) * K_DIM + aCol;
    const float* bg = mu + (size_t)bRow * N_DIM + block_n + bCol;

    float acc[TM][TN];
    #pragma unroll
    for (int i = 0; i < TM; i++)
        #pragma unroll
        for (int j = 0; j < TN; j++) acc[i][j] = 0.f;

    for (int k0 = 0; k0 < K_DIM; k0 += BK) {
        // ---- load A (2 x float4), scatter transposed into As
        float4 a0 = *(const float4*)(xg);
        float4 a1 = *(const float4*)(xg + (size_t)64 * K_DIM);
        As[aCol + 0][aRow] = a0.x;
        As[aCol + 1][aRow] = a0.y;
        As[aCol + 2][aRow] = a0.z;
        As[aCol + 3][aRow] = a0.w;
        As[aCol + 0][aRow + 64] = a1.x;
        As[aCol + 1][aRow + 64] = a1.y;
        As[aCol + 2][aRow + 64] = a1.z;
        As[aCol + 3][aRow + 64] = a1.w;

        // ---- load B (2 x float4), direct
        float4 b0 = *(const float4*)(bg);
        float4 b1 = *(const float4*)(bg + (size_t)8 * N_DIM);
        *(float4*)&Bs[bRow][bCol]     = b0;
        *(float4*)&Bs[bRow + 8][bCol] = b1;

        __syncthreads();

        #pragma unroll
        for (int k = 0; k < BK; k++) {
            float a_frag[TM], b_frag[TN];
            #pragma unroll
            for (int i = 0; i < TM; i += 4)
                *(float4*)&a_frag[i] = *(const float4*)&As[k][ty * TM + i];
            #pragma unroll
            for (int j = 0; j < TN; j += 4)
                *(float4*)&b_frag[j] = *(const float4*)&Bs[k][tx * TN + j];
            #pragma unroll
            for (int i = 0; i < TM; i++)
                #pragma unroll
                for (int j = 0; j < TN; j++)
                    acc[i][j] = fmaf(a_frag[i], b_frag[j], acc[i][j]);
        }

        __syncthreads();
        xg += BK;
        bg += (size_t)BK * N_DIM;
    }

    const float gamma = *gamma_p;

    // epilogue: RBF transform + store (float4)
    #pragma unroll
    for (int i = 0; i < TM; i++) {
        const int m = block_m + ty * TM + i;
        const float xs = g_xsq[m];
        #pragma unroll
        for (int j = 0; j < TN; j += 4) {
            const int n = block_n + tx * TN + j;
            float4 r;
            r.x = expf(-gamma * (xs + g_musq[n + 0] - 2.f * acc[i][j + 0]));
            r.y = expf(-gamma * (xs + g_musq[n + 1] - 2.f * acc[i][j + 1]));
            r.z = expf(-gamma * (xs + g_musq[n + 2] - 2.f * acc[i][j + 2]));
            r.w = expf(-gamma * (xs + g_musq[n + 3] - 2.f * acc[i][j + 3]));
            *(float4*)&out[(size_t)m * N_DIM + n] = r;
        }
    }
}

// ---------------------------------------------------------------------------
// Launch: inputs per metadata order: x (B*K f32), mu (K*U f32), gamma (1 f32)
// ---------------------------------------------------------------------------
extern "C" void kernel_launch(void* const* d_in, const int* in_sizes, int n_in,
                              void* d_out, int out_size) {
    const float* x     = (const float*)d_in[0];
    const float* mu    = (const float*)d_in[1];
    const float* gamma = (const float*)d_in[2];
    float* out = (float*)d_out;

    xsq_kernel<<<B_DIM, 256>>>(x);
    musq_kernel<<<(N_DIM + 255) / 256, 256>>>(mu);

    dim3 grid(N_DIM / BN, B_DIM / BM);
    rbf_gemm_kernel<<<grid, 256>>>(x, mu, gamma, out);
}

// round 2
// speedup vs baseline: 8.2036x; 8.2036x over previous
#include <cuda_runtime.h>
#include <math.h>

// Problem dims (fixed by the dataset): x (B, K), mu (K, U), out (B, U)
#define B_DIM 8192
#define K_DIM 1024
#define N_DIM 4096

// GEMM tiling (fallback path)
#define BM 128
#define BN 128
#define BK 16
#define TM 8
#define TN 8
#define APAD 4

// Underflow threshold: exp(-t) with t > ~104 rounds to 0 in fp32
// (min denormal 2^-149 ~ 1.4e-45; ln(0.7e-45) ~ -103.9). Use margin.
#define UNDERFLOW_T 118.0f

// Scratch for row/col squared norms (no allocations allowed -> device globals)
__device__ float g_xsq[B_DIM];
__device__ float g_musq[N_DIM];

// ---------------------------------------------------------------------------
// ||x_row||^2 : one block per row, 256 threads, warp+block reduce
// ---------------------------------------------------------------------------
__global__ __launch_bounds__(256) void xsq_kernel(const float* __restrict__ x) {
    int row = blockIdx.x;
    const float4* xr = (const float4*)(x + (size_t)row * K_DIM);
    float s = 0.f;
    for (int i = threadIdx.x; i < K_DIM / 4; i += 256) {
        float4 v = xr[i];
        s += v.x * v.x + v.y * v.y + v.z * v.z + v.w * v.w;
    }
    __shared__ float sm[8];
    #pragma unroll
    for (int o = 16; o > 0; o >>= 1) s += __shfl_xor_sync(0xffffffffu, s, o);
    if ((threadIdx.x & 31) == 0) sm[threadIdx.x >> 5] = s;
    __syncthreads();
    if (threadIdx.x < 32) {
        s = (threadIdx.x < 8) ? sm[threadIdx.x] : 0.f;
        #pragma unroll
        for (int o = 4; o > 0; o >>= 1) s += __shfl_xor_sync(0xffffffffu, s, o);
        if (threadIdx.x == 0) g_xsq[row] = s;
    }
}

// ---------------------------------------------------------------------------
// ||mu_col||^2 : one thread per column, coalesced across K
// ---------------------------------------------------------------------------
__global__ __launch_bounds__(256) void musq_kernel(const float* __restrict__ mu) {
    int n = blockIdx.x * 256 + threadIdx.x;
    if (n >= N_DIM) return;
    float s = 0.f;
    #pragma unroll 4
    for (int k = 0; k < K_DIM; k++) {
        float v = mu[(size_t)k * N_DIM + n];
        s += v * v;
    }
    g_musq[n] = s;
}

// ---------------------------------------------------------------------------
// Guarded fused kernel. Per 128x128 output tile:
//   bound = (min_m ||x_m|| - max_n ||mu_n||)^2   (valid when difference > 0)
//   l2(m,n) >= bound for every pair in the tile. If gamma*bound > 118,
//   every exp() underflows to 0 in fp32 -> write zeros, skip the GEMM.
//   Otherwise compute the exact fp32 GEMM + RBF epilogue (always correct).
// ---------------------------------------------------------------------------
__global__ __launch_bounds__(256) void rbf_guarded_kernel(
    const float* __restrict__ x,
    const float* __restrict__ mu,
    const float* __restrict__ gamma_p,
    float* __restrict__ out)
{
    __shared__ float As[BK][BM + APAD];
    __shared__ float Bs[BK][BN];
    __shared__ float red[256];
    __shared__ int skip;

    const int tid = threadIdx.x;
    const int block_m = blockIdx.y * BM;
    const int block_n = blockIdx.x * BN;
    const float gamma = *gamma_p;

    // ---- tile bound: red[0..127] -> min xsq, red[128..255] -> min(-musq)
    if (tid < 128) red[tid] = g_xsq[block_m + tid];
    else           red[tid] = -g_musq[block_n + (tid - 128)];
    __syncthreads();
    #pragma unroll
    for (int s = 64; s > 0; s >>= 1) {
        if ((tid & 127) < s) red[tid] = fminf(red[tid], red[tid + s]);
        __syncthreads();
    }
    if (tid == 0) {
        float rx = sqrtf(fmaxf(red[0], 0.f));     // min row norm in tile
        float rm = sqrtf(fmaxf(-red[128], 0.f));  // max col norm in tile
        float d = rx - rm;
        skip = (gamma > 0.f && d > 0.f && gamma * d * d > UNDERFLOW_T) ? 1 : 0;
    }
    __syncthreads();

    if (skip) {
        // Entire tile provably underflows -> coalesced float4 zero stores.
        float4 z = make_float4(0.f, 0.f, 0.f, 0.f);
        const int c4 = tid & 31;          // 0..31 float4 columns
        for (int r = tid >> 5; r < BM; r += 8) {
            float4* o4 = (float4*)(out + (size_t)(block_m + r) * N_DIM + block_n);
            o4[c4] = z;
        }
        return;
    }

    // ---------------- fallback: exact fp32 GEMM + RBF ----------------
    const int aRow = tid >> 2;
    const int aCol = (tid & 3) * 4;
    const int bRow = tid >> 5;
    const int bCol = (tid & 31) * 4;
    const int ty = tid >> 4;
    const int tx = tid & 15;

    const float* xg = x + (size_t)(block_m + aRow) * K_DIM + aCol;
    const float* bg = mu + (size_t)bRow * N_DIM + block_n + bCol;

    float acc[TM][TN];
    #pragma unroll
    for (int i = 0; i < TM; i++)
        #pragma unroll
        for (int j = 0; j < TN; j++) acc[i][j] = 0.f;

    for (int k0 = 0; k0 < K_DIM; k0 += BK) {
        float4 a0 = *(const float4*)(xg);
        float4 a1 = *(const float4*)(xg + (size_t)64 * K_DIM);
        As[aCol + 0][aRow] = a0.x;
        As[aCol + 1][aRow] = a0.y;
        As[aCol + 2][aRow] = a0.z;
        As[aCol + 3][aRow] = a0.w;
        As[aCol + 0][aRow + 64] = a1.x;
        As[aCol + 1][aRow + 64] = a1.y;
        As[aCol + 2][aRow + 64] = a1.z;
        As[aCol + 3][aRow + 64] = a1.w;

        float4 b0 = *(const float4*)(bg);
        float4 b1 = *(const float4*)(bg + (size_t)8 * N_DIM);
        *(float4*)&Bs[bRow][bCol]     = b0;
        *(float4*)&Bs[bRow + 8][bCol] = b1;

        __syncthreads();

        #pragma unroll
        for (int k = 0; k < BK; k++) {
            float a_frag[TM], b_frag[TN];
            #pragma unroll
            for (int i = 0; i < TM; i += 4)
                *(float4*)&a_frag[i] = *(const float4*)&As[k][ty * TM + i];
            #pragma unroll
            for (int j = 0; j < TN; j += 4)
                *(float4*)&b_frag[j] = *(const float4*)&Bs[k][tx * TN + j];
            #pragma unroll
            for (int i = 0; i < TM; i++)
                #pragma unroll
                for (int j = 0; j < TN; j++)
                    acc[i][j] = fmaf(a_frag[i], b_frag[j], acc[i][j]);
        }

        __syncthreads();
        xg += BK;
        bg += (size_t)BK * N_DIM;
    }

    #pragma unroll
    for (int i = 0; i < TM; i++) {
        const int m = block_m + ty * TM + i;
        const float xs = g_xsq[m];
        #pragma unroll
        for (int j = 0; j < TN; j += 4) {
            const int n = block_n + tx * TN + j;
            float4 r;
            r.x = expf(-gamma * (xs + g_musq[n + 0] - 2.f * acc[i][j + 0]));
            r.y = expf(-gamma * (xs + g_musq[n + 1] - 2.f * acc[i][j + 1]));
            r.z = expf(-gamma * (xs + g_musq[n + 2] - 2.f * acc[i][j + 2]));
            r.w = expf(-gamma * (xs + g_musq[n + 3] - 2.f * acc[i][j + 3]));
            *(float4*)&out[(size_t)m * N_DIM + n] = r;
        }
    }
}

// ---------------------------------------------------------------------------
// Launch: inputs per metadata order: x (B*K f32), mu (K*U f32), gamma (1 f32)
// ---------------------------------------------------------------------------
extern "C" void kernel_launch(void* const* d_in, const int* in_sizes, int n_in,
                              void* d_out, int out_size) {
    const float* x     = (const float*)d_in[0];
    const float* mu    = (const float*)d_in[1];
    const float* gamma = (const float*)d_in[2];
    float* out = (float*)d_out;

    xsq_kernel<<<B_DIM, 256>>>(x);
    musq_kernel<<<(N_DIM + 255) / 256, 256>>>(mu);

    dim3 grid(N_DIM / BN, B_DIM / BM);
    rbf_guarded_kernel<<<grid, 256>>>(x, mu, gamma, out);
}

// round 3
// speedup vs baseline: 32.7967x; 3.9979x over previous
#include <cuda_runtime.h>
#include <math.h>

// Problem dims (fixed by the dataset): x (B, K), mu (K, U), out (B, U)
#define B_DIM 8192
#define K_DIM 1024
#define N_DIM 4096

// GEMM tiling (fallback path)
#define BM 128
#define BN 128
#define BK 16
#define TM 8
#define TN 8
#define APAD 4

// Underflow threshold: exp(-t) with t > ~104 rounds to 0 in fp32
#define UNDERFLOW_T 118.0f

// Scratch for row/col squared norms (no allocations allowed -> device globals)
__device__ float g_xsq[B_DIM];
__device__ float g_musq[N_DIM];

// ---------------------------------------------------------------------------
// Fused norms kernel.
//   Blocks [0, 1024):   xsq — one warp per x row, 8 float4 loads per lane,
//                       shuffle-only reduce (no block barriers).
//   Blocks [1024, 1152): musq — 32 columns x 8 K-slices per CTA, coalesced.
// ---------------------------------------------------------------------------
#define XSQ_BLOCKS (B_DIM / 8)            // 1024
#define MUSQ_BLOCKS (N_DIM / 32)          // 128
#define NORM_BLOCKS (XSQ_BLOCKS + MUSQ_BLOCKS)

__global__ __launch_bounds__(256) void norms_kernel(
    const float* __restrict__ x, const float* __restrict__ mu)
{
    const int tid = threadIdx.x;
    if (blockIdx.x < XSQ_BLOCKS) {
        // ---- xsq: warp w handles row blockIdx*8 + w
        const int warp = tid >> 5, lane = tid & 31;
        const int row = blockIdx.x * 8 + warp;
        const float4* xr = (const float4*)(x + (size_t)row * K_DIM);
        float s = 0.f;
        #pragma unroll
        for (int i = 0; i < 8; i++) {          // 256 float4 per row / 32 lanes
            float4 v = xr[lane + 32 * i];
            s += v.x * v.x + v.y * v.y + v.z * v.z + v.w * v.w;
        }
        #pragma unroll
        for (int o = 16; o > 0; o >>= 1) s += __shfl_xor_sync(0xffffffffu, s, o);
        if (lane == 0) g_xsq[row] = s;
    } else {
        // ---- musq: CTA covers 32 columns; 8 K-slices of 128 rows each
        const int cb = (blockIdx.x - XSQ_BLOCKS) * 32;
        const int col = cb + (tid & 31);
        const int ks = tid >> 5;               // 0..7
        const float* p = mu + (size_t)(ks * 128) * N_DIM + col;
        float s = 0.f;
        #pragma unroll 8
        for (int i = 0; i < 128; i++) {
            float v = p[(size_t)i * N_DIM];
            s += v * v;
        }
        __shared__ float sm[8][32];
        sm[ks][tid & 31] = s;
        __syncthreads();
        if (tid < 32) {
            float t = 0.f;
            #pragma unroll
            for (int k = 0; k < 8; k++) t += sm[k][tid];
            g_musq[cb + tid] = t;
        }
    }
}

// ---------------------------------------------------------------------------
// Guarded fused kernel. Per 128x128 output tile:
//   bound = (min_m ||x_m|| - max_n ||mu_n||)^2
//   If gamma*bound > 118 every exp() underflows to fp32 zero -> write zeros.
//   Otherwise compute the exact fp32 GEMM + RBF epilogue.
// ---------------------------------------------------------------------------
__global__ __launch_bounds__(256) void rbf_guarded_kernel(
    const float* __restrict__ x,
    const float* __restrict__ mu,
    const float* __restrict__ gamma_p,
    float* __restrict__ out)
{
    __shared__ float As[BK][BM + APAD];
    __shared__ float Bs[BK][BN];
    __shared__ float wmin[8];
    __shared__ int skip;

    const int tid = threadIdx.x;
    const int block_m = blockIdx.y * BM;
    const int block_n = blockIdx.x * BN;
    const float gamma = *gamma_p;

    // ---- cheap tile guard: warp shuffle mins + one combine
    {
        // threads 0..127 -> xsq values, 128..255 -> -musq values
        float v = (tid < 128) ? g_xsq[block_m + tid]
                              : -g_musq[block_n + (tid - 128)];
        #pragma unroll
        for (int o = 16; o > 0; o >>= 1)
            v = fminf(v, __shfl_xor_sync(0xffffffffu, v, o));
        if ((tid & 31) == 0) wmin[tid >> 5] = v;
        __syncthreads();
        if (tid == 0) {
            float mn_x = fminf(fminf(wmin[0], wmin[1]), fminf(wmin[2], wmin[3]));
            float mx_mu = -fminf(fminf(wmin[4], wmin[5]), fminf(wmin[6], wmin[7]));
            float d = sqrtf(fmaxf(mn_x, 0.f)) - sqrtf(fmaxf(mx_mu, 0.f));
            skip = (gamma > 0.f && d > 0.f && gamma * d * d > UNDERFLOW_T) ? 1 : 0;
        }
        __syncthreads();
    }

    if (skip) {
        // Entire tile provably underflows -> coalesced float4 zero stores.
        float4 z = make_float4(0.f, 0.f, 0.f, 0.f);
        const int c4 = tid & 31;
        #pragma unroll
        for (int r = tid >> 5; r < BM; r += 8) {
            float4* o4 = (float4*)(out + (size_t)(block_m + r) * N_DIM + block_n);
            o4[c4] = z;
        }
        return;
    }

    // ---------------- fallback: exact fp32 GEMM + RBF ----------------
    const int aRow = tid >> 2;
    const int aCol = (tid & 3) * 4;
    const int bRow = tid >> 5;
    const int bCol = (tid & 31) * 4;
    const int ty = tid >> 4;
    const int tx = tid & 15;

    const float* xg = x + (size_t)(block_m + aRow) * K_DIM + aCol;
    const float* bg = mu + (size_t)bRow * N_DIM + block_n + bCol;

    float acc[TM][TN];
    #pragma unroll
    for (int i = 0; i < TM; i++)
        #pragma unroll
        for (int j = 0; j < TN; j++) acc[i][j] = 0.f;

    for (int k0 = 0; k0 < K_DIM; k0 += BK) {
        float4 a0 = *(const float4*)(xg);
        float4 a1 = *(const float4*)(xg + (size_t)64 * K_DIM);
        As[aCol + 0][aRow] = a0.x;
        As[aCol + 1][aRow] = a0.y;
        As[aCol + 2][aRow] = a0.z;
        As[aCol + 3][aRow] = a0.w;
        As[aCol + 0][aRow + 64] = a1.x;
        As[aCol + 1][aRow + 64] = a1.y;
        As[aCol + 2][aRow + 64] = a1.z;
        As[aCol + 3][aRow + 64] = a1.w;

        float4 b0 = *(const float4*)(bg);
        float4 b1 = *(const float4*)(bg + (size_t)8 * N_DIM);
        *(float4*)&Bs[bRow][bCol]     = b0;
        *(float4*)&Bs[bRow + 8][bCol] = b1;

        __syncthreads();

        #pragma unroll
        for (int k = 0; k < BK; k++) {
            float a_frag[TM], b_frag[TN];
            #pragma unroll
            for (int i = 0; i < TM; i += 4)
                *(float4*)&a_frag[i] = *(const float4*)&As[k][ty * TM + i];
            #pragma unroll
            for (int j = 0; j < TN; j += 4)
                *(float4*)&b_frag[j] = *(const float4*)&Bs[k][tx * TN + j];
            #pragma unroll
            for (int i = 0; i < TM; i++)
                #pragma unroll
                for (int j = 0; j < TN; j++)
                    acc[i][j] = fmaf(a_frag[i], b_frag[j], acc[i][j]);
        }

        __syncthreads();
        xg += BK;
        bg += (size_t)BK * N_DIM;
    }

    #pragma unroll
    for (int i = 0; i < TM; i++) {
        const int m = block_m + ty * TM + i;
        const float xs = g_xsq[m];
        #pragma unroll
        for (int j = 0; j < TN; j += 4) {
            const int n = block_n + tx * TN + j;
            float4 r;
            r.x = expf(-gamma * (xs + g_musq[n + 0] - 2.f * acc[i][j + 0]));
            r.y = expf(-gamma * (xs + g_musq[n + 1] - 2.f * acc[i][j + 1]));
            r.z = expf(-gamma * (xs + g_musq[n + 2] - 2.f * acc[i][j + 2]));
            r.w = expf(-gamma * (xs + g_musq[n + 3] - 2.f * acc[i][j + 3]));
            *(float4*)&out[(size_t)m * N_DIM + n] = r;
        }
    }
}

// ---------------------------------------------------------------------------
// Launch: inputs per metadata order: x (B*K f32), mu (K*U f32), gamma (1 f32)
// ---------------------------------------------------------------------------
extern "C" void kernel_launch(void* const* d_in, const int* in_sizes, int n_in,
                              void* d_out, int out_size) {
    const float* x     = (const float*)d_in[0];
    const float* mu    = (const float*)d_in[1];
    const float* gamma = (const float*)d_in[2];
    float* out = (float*)d_out;

    norms_kernel<<<NORM_BLOCKS, 256>>>(x, mu);

    dim3 grid(N_DIM / BN, B_DIM / BM);
    rbf_guarded_kernel<<<grid, 256>>>(x, mu, gamma, out);
}

// round 4
// speedup vs baseline: 33.7317x; 1.0285x over previous
#include <cuda_runtime.h>
#include <math.h>

// Problem dims (fixed by the dataset): x (B, K), mu (K, U), out (B, U)
#define B_DIM 8192
#define K_DIM 1024
#define N_DIM 4096

// GEMM tiling (fallback path)
#define BM 128
#define BN 128
#define BK 16
#define TM 8
#define TN 8
#define APAD 4

#define MTILES (B_DIM / BM)   // 64
#define NTILES (N_DIM / BN)   // 32

// Underflow threshold: exp(-t) with t > ~104 rounds to 0 in fp32
#define UNDERFLOW_T 118.0f

// Scratch (no allocations allowed -> device globals)
__device__ float g_xsq[B_DIM];
__device__ float g_musq[N_DIM];
__device__ unsigned int g_xmin_tile[MTILES];   // min ||x||^2 per 128-row tile (bits)
__device__ unsigned int g_mumax_tile[NTILES];  // max ||mu||^2 per 128-col tile (bits)

// ---------------------------------------------------------------------------
// Fill kernel: zero the whole output (correct value for every tile that the
// guard later proves underflows) and init the per-tile guard slots.
// ---------------------------------------------------------------------------
#define FILL_BLOCKS 1024
__global__ __launch_bounds__(256) void fill_kernel(float4* __restrict__ out) {
    if (blockIdx.x == 0) {
        if (threadIdx.x < MTILES) g_xmin_tile[threadIdx.x] = 0x7F800000u;  // +inf
        else if (threadIdx.x < MTILES + NTILES) g_mumax_tile[threadIdx.x - MTILES] = 0u;
    }
    const float4 z = make_float4(0.f, 0.f, 0.f, 0.f);
    const size_t total = (size_t)B_DIM * N_DIM / 4;           // 8M float4
    const size_t stride = (size_t)FILL_BLOCKS * 256;
    for (size_t i = (size_t)blockIdx.x * 256 + threadIdx.x; i < total; i += stride)
        out[i] = z;
}

// ---------------------------------------------------------------------------
// Fused norms kernel.
//   Blocks [0, 1024):    xsq — one warp per x row + tile-row atomicMin
//   Blocks [1024, 1536): musq — 8 cols x 32 K-slices per CTA + tile-col atomicMax
// Non-negative floats: bit pattern is order-preserving -> uint atomics.
// ---------------------------------------------------------------------------
#define XSQ_BLOCKS (B_DIM / 8)            // 1024
#define MUSQ_BLOCKS (N_DIM / 8)           // 512
#define NORM_BLOCKS (XSQ_BLOCKS + MUSQ_BLOCKS)

__global__ __launch_bounds__(256) void norms_kernel(
    const float* __restrict__ x, const float* __restrict__ mu)
{
    const int tid = threadIdx.x;
    if (blockIdx.x < XSQ_BLOCKS) {
        // ---- xsq: warp w handles row blockIdx*8 + w
        const int warp = tid >> 5, lane = tid & 31;
        const int row = blockIdx.x * 8 + warp;
        const float4* xr = (const float4*)(x + (size_t)row * K_DIM);
        float s = 0.f;
        #pragma unroll
        for (int i = 0; i < 8; i++) {
            float4 v = xr[lane + 32 * i];
            s += v.x * v.x + v.y * v.y + v.z * v.z + v.w * v.w;
        }
        #pragma unroll
        for (int o = 16; o > 0; o >>= 1) s += __shfl_xor_sync(0xffffffffu, s, o);
        if (lane == 0) {
            g_xsq[row] = s;
            atomicMin(&g_xmin_tile[row >> 7], __float_as_uint(s));
        }
    } else {
        // ---- musq: CTA covers 8 columns; 32 K-slices of 32 rows each
        const int cb = (blockIdx.x - XSQ_BLOCKS) * 8;
        const int col = cb + (tid & 7);
        const int ks = tid >> 3;               // 0..31
        const float* p = mu + (size_t)(ks * 32) * N_DIM + col;
        float s = 0.f;
        #pragma unroll 8
        for (int i = 0; i < 32; i++) {
            float v = p[(size_t)i * N_DIM];
            s += v * v;
        }
        __shared__ float sm[32][8];
        sm[ks][tid & 7] = s;
        __syncthreads();
        if (tid < 8) {
            float t = 0.f;
            #pragma unroll
            for (int k = 0; k < 32; k++) t += sm[k][tid];
            g_musq[cb + tid] = t;
            atomicMax(&g_mumax_tile[(cb + tid) >> 7], __float_as_uint(t));
        }
    }
}

// ---------------------------------------------------------------------------
// Guarded GEMM kernel. Per 128x128 output tile:
//   bound = (sqrt(min_m ||x_m||^2) - sqrt(max_n ||mu_n||^2))^2  (2 scalar loads)
//   If gamma*bound > 118 every exp() underflows to fp32 zero; output already
//   zeroed by fill_kernel -> return immediately.
//   Otherwise compute the exact fp32 GEMM + RBF epilogue (always correct).
// ---------------------------------------------------------------------------
__global__ __launch_bounds__(256) void rbf_guarded_kernel(
    const float* __restrict__ x,
    const float* __restrict__ mu,
    const float* __restrict__ gamma_p,
    float* __restrict__ out)
{
    const int tid = threadIdx.x;
    const int block_m = blockIdx.y * BM;
    const int block_n = blockIdx.x * BN;
    const float gamma = *gamma_p;

    {
        float mn_x = __uint_as_float(g_xmin_tile[blockIdx.y]);
        float mx_mu = __uint_as_float(g_mumax_tile[blockIdx.x]);
        float d = sqrtf(fmaxf(mn_x, 0.f)) - sqrtf(fmaxf(mx_mu, 0.f));
        if (gamma > 0.f && d > 0.f && gamma * d * d > UNDERFLOW_T)
            return;  // tile provably all-zero; fill_kernel already wrote it
    }

    // ---------------- fallback: exact fp32 GEMM + RBF ----------------
    __shared__ float As[BK][BM + APAD];
    __shared__ float Bs[BK][BN];

    const int aRow = tid >> 2;
    const int aCol = (tid & 3) * 4;
    const int bRow = tid >> 5;
    const int bCol = (tid & 31) * 4;
    const int ty = tid >> 4;
    const int tx = tid & 15;

    const float* xg = x + (size_t)(block_m + aRow) * K_DIM + aCol;
    const float* bg = mu + (size_t)bRow * N_DIM + block_n + bCol;

    float acc[TM][TN];
    #pragma unroll
    for (int i = 0; i < TM; i++)
        #pragma unroll
        for (int j = 0; j < TN; j++) acc[i][j] = 0.f;

    for (int k0 = 0; k0 < K_DIM; k0 += BK) {
        float4 a0 = *(const float4*)(xg);
        float4 a1 = *(const float4*)(xg + (size_t)64 * K_DIM);
        As[aCol + 0][aRow] = a0.x;
        As[aCol + 1][aRow] = a0.y;
        As[aCol + 2][aRow] = a0.z;
        As[aCol + 3][aRow] = a0.w;
        As[aCol + 0][aRow + 64] = a1.x;
        As[aCol + 1][aRow + 64] = a1.y;
        As[aCol + 2][aRow + 64] = a1.z;
        As[aCol + 3][aRow + 64] = a1.w;

        float4 b0 = *(const float4*)(bg);
        float4 b1 = *(const float4*)(bg + (size_t)8 * N_DIM);
        *(float4*)&Bs[bRow][bCol]     = b0;
        *(float4*)&Bs[bRow + 8][bCol] = b1;

        __syncthreads();

        #pragma unroll
        for (int k = 0; k < BK; k++) {
            float a_frag[TM], b_frag[TN];
            #pragma unroll
            for (int i = 0; i < TM; i += 4)
                *(float4*)&a_frag[i] = *(const float4*)&As[k][ty * TM + i];
            #pragma unroll
            for (int j = 0; j < TN; j += 4)
                *(float4*)&b_frag[j] = *(const float4*)&Bs[k][tx * TN + j];
            #pragma unroll
            for (int i = 0; i < TM; i++)
                #pragma unroll
                for (int j = 0; j < TN; j++)
                    acc[i][j] = fmaf(a_frag[i], b_frag[j], acc[i][j]);
        }

        __syncthreads();
        xg += BK;
        bg += (size_t)BK * N_DIM;
    }

    #pragma unroll
    for (int i = 0; i < TM; i++) {
        const int m = block_m + ty * TM + i;
        const float xs = g_xsq[m];
        #pragma unroll
        for (int j = 0; j < TN; j += 4) {
            const int n = block_n + tx * TN + j;
            float4 r;
            r.x = expf(-gamma * (xs + g_musq[n + 0] - 2.f * acc[i][j + 0]));
            r.y = expf(-gamma * (xs + g_musq[n + 1] - 2.f * acc[i][j + 1]));
            r.z = expf(-gamma * (xs + g_musq[n + 2] - 2.f * acc[i][j + 2]));
            r.w = expf(-gamma * (xs + g_musq[n + 3] - 2.f * acc[i][j + 3]));
            *(float4*)&out[(size_t)m * N_DIM + n] = r;
        }
    }
}

// ---------------------------------------------------------------------------
// Launch: inputs per metadata order: x (B*K f32), mu (K*U f32), gamma (1 f32)
// ---------------------------------------------------------------------------
extern "C" void kernel_launch(void* const* d_in, const int* in_sizes, int n_in,
                              void* d_out, int out_size) {
    const float* x     = (const float*)d_in[0];
    const float* mu    = (const float*)d_in[1];
    const float* gamma = (const float*)d_in[2];
    float* out = (float*)d_out;

    fill_kernel<<<FILL_BLOCKS, 256>>>((float4*)out);
    norms_kernel<<<NORM_BLOCKS, 256>>>(x, mu);

    dim3 grid(NTILES, MTILES);
    rbf_guarded_kernel<<<grid, 256>>>(x, mu, gamma, out);
}

// round 5
// speedup vs baseline: 38.1679x; 1.1315x over previous
#include <cuda_runtime.h>
#include <math.h>

// Problem dims (fixed by the dataset): x (B, K), mu (K, U), out (B, U)
#define B_DIM 8192
#define K_DIM 1024
#define N_DIM 4096

// GEMM tiling (fallback path)
#define BM 128
#define BN 128
#define BK 16
#define TM 8
#define TN 8
#define APAD 4

#define MTILES (B_DIM / BM)   // 64
#define NTILES (N_DIM / BN)   // 32

// Underflow threshold: exp(-t) with t > ~104 rounds to 0 in fp32
#define UNDERFLOW_T 118.0f

// Scratch (no allocations allowed -> device globals)
__device__ float g_xsq[B_DIM];
__device__ float g_musq[N_DIM];
__device__ unsigned int g_xmin_tile[MTILES];   // min ||x||^2 per 128-row tile (bits)
__device__ unsigned int g_mumax_tile[NTILES];  // max ||mu||^2 per 128-col tile (bits)

// ---------------------------------------------------------------------------
// Fused prep kernel: norms (reads) + zero-fill (writes) in one launch so both
// DRAM directions are busy simultaneously.
//   Blocks [0, 1024):            xsq  — one warp per x row + tile atomicMin
//   Blocks [1024, 1536):         musq — 8 cols x 32 K-slices + tile atomicMax
//   Blocks [1536, 1536+2048):    fill — streaming zero stores (__stcs)
// Non-negative floats: bit pattern is order-preserving -> uint atomics.
// ---------------------------------------------------------------------------
#define XSQ_BLOCKS (B_DIM / 8)            // 1024
#define MUSQ_BLOCKS (N_DIM / 8)           // 512
#define FILL_BLOCKS 2048
#define PREP_BLOCKS (XSQ_BLOCKS + MUSQ_BLOCKS + FILL_BLOCKS)

__global__ __launch_bounds__(256) void prep_kernel(
    const float* __restrict__ x, const float* __restrict__ mu,
    float4* __restrict__ out)
{
    const int tid = threadIdx.x;
    if (blockIdx.x < XSQ_BLOCKS) {
        // ---- xsq: warp w handles row blockIdx*8 + w
        const int warp = tid >> 5, lane = tid & 31;
        const int row = blockIdx.x * 8 + warp;
        const float4* xr = (const float4*)(x + (size_t)row * K_DIM);
        float s = 0.f;
        #pragma unroll
        for (int i = 0; i < 8; i++) {
            float4 v = xr[lane + 32 * i];
            s += v.x * v.x + v.y * v.y + v.z * v.z + v.w * v.w;
        }
        #pragma unroll
        for (int o = 16; o > 0; o >>= 1) s += __shfl_xor_sync(0xffffffffu, s, o);
        if (lane == 0) {
            g_xsq[row] = s;
            atomicMin(&g_xmin_tile[row >> 7], __float_as_uint(s));
        }
    } else if (blockIdx.x < XSQ_BLOCKS + MUSQ_BLOCKS) {
        // ---- musq: CTA covers 8 columns; 32 K-slices of 32 rows each
        const int cb = (blockIdx.x - XSQ_BLOCKS) * 8;
        const int col = cb + (tid & 7);
        const int ks = tid >> 3;               // 0..31
        const float* p = mu + (size_t)(ks * 32) * N_DIM + col;
        float s = 0.f;
        #pragma unroll 8
        for (int i = 0; i < 32; i++) {
            float v = p[(size_t)i * N_DIM];
            s += v * v;
        }
        __shared__ float sm[32][8];
        sm[ks][tid & 7] = s;
        __syncthreads();
        if (tid < 8) {
            float t = 0.f;
            #pragma unroll
            for (int k = 0; k < 32; k++) t += sm[k][tid];
            g_musq[cb + tid] = t;
            atomicMax(&g_mumax_tile[(cb + tid) >> 7], __float_as_uint(t));
        }
    } else {
        // ---- fill: streaming zero stores, 16 float4 per thread
        const int fb = blockIdx.x - (XSQ_BLOCKS + MUSQ_BLOCKS);
        const float4 z = make_float4(0.f, 0.f, 0.f, 0.f);
        const size_t total = (size_t)B_DIM * N_DIM / 4;       // 8M float4
        const size_t stride = (size_t)FILL_BLOCKS * 256;
        for (size_t i = (size_t)fb * 256 + tid; i < total; i += stride)
            __stcs(&out[i], z);
    }
}

// ---------------------------------------------------------------------------
// Guarded GEMM kernel. Per 128x128 output tile:
//   bound = (sqrt(min_m ||x_m||^2) - sqrt(max_n ||mu_n||^2))^2  (2 scalar loads)
//   If gamma*bound > 118 every exp() underflows to fp32 zero; output already
//   zeroed by prep_kernel -> return immediately.
//   Otherwise compute the exact fp32 GEMM + RBF epilogue (always correct).
// ---------------------------------------------------------------------------
__global__ __launch_bounds__(256) void rbf_guarded_kernel(
    const float* __restrict__ x,
    const float* __restrict__ mu,
    const float* __restrict__ gamma_p,
    float* __restrict__ out)
{
    const int tid = threadIdx.x;
    const int block_m = blockIdx.y * BM;
    const int block_n = blockIdx.x * BN;
    const float gamma = *gamma_p;

    {
        float mn_x = __uint_as_float(g_xmin_tile[blockIdx.y]);
        float mx_mu = __uint_as_float(g_mumax_tile[blockIdx.x]);
        float d = sqrtf(fmaxf(mn_x, 0.f)) - sqrtf(fmaxf(mx_mu, 0.f));
        if (gamma > 0.f && d > 0.f && gamma * d * d > UNDERFLOW_T)
            return;  // tile provably all-zero; prep_kernel already wrote it
    }

    // ---------------- fallback: exact fp32 GEMM + RBF ----------------
    __shared__ float As[BK][BM + APAD];
    __shared__ float Bs[BK][BN];

    const int aRow = tid >> 2;
    const int aCol = (tid & 3) * 4;
    const int bRow = tid >> 5;
    const int bCol = (tid & 31) * 4;
    const int ty = tid >> 4;
    const int tx = tid & 15;

    const float* xg = x + (size_t)(block_m + aRow) * K_DIM + aCol;
    const float* bg = mu + (size_t)bRow * N_DIM + block_n + bCol;

    float acc[TM][TN];
    #pragma unroll
    for (int i = 0; i < TM; i++)
        #pragma unroll
        for (int j = 0; j < TN; j++) acc[i][j] = 0.f;

    for (int k0 = 0; k0 < K_DIM; k0 += BK) {
        float4 a0 = *(const float4*)(xg);
        float4 a1 = *(const float4*)(xg + (size_t)64 * K_DIM);
        As[aCol + 0][aRow] = a0.x;
        As[aCol + 1][aRow] = a0.y;
        As[aCol + 2][aRow] = a0.z;
        As[aCol + 3][aRow] = a0.w;
        As[aCol + 0][aRow + 64] = a1.x;
        As[aCol + 1][aRow + 64] = a1.y;
        As[aCol + 2][aRow + 64] = a1.z;
        As[aCol + 3][aRow + 64] = a1.w;

        float4 b0 = *(const float4*)(bg);
        float4 b1 = *(const float4*)(bg + (size_t)8 * N_DIM);
        *(float4*)&Bs[bRow][bCol]     = b0;
        *(float4*)&Bs[bRow + 8][bCol] = b1;

        __syncthreads();

        #pragma unroll
        for (int k = 0; k < BK; k++) {
            float a_frag[TM], b_frag[TN];
            #pragma unroll
            for (int i = 0; i < TM; i += 4)
                *(float4*)&a_frag[i] = *(const float4*)&As[k][ty * TM + i];
            #pragma unroll
            for (int j = 0; j < TN; j += 4)
                *(float4*)&b_frag[j] = *(const float4*)&Bs[k][tx * TN + j];
            #pragma unroll
            for (int i = 0; i < TM; i++)
                #pragma unroll
                for (int j = 0; j < TN; j++)
                    acc[i][j] = fmaf(a_frag[i], b_frag[j], acc[i][j]);
        }

        __syncthreads();
        xg += BK;
        bg += (size_t)BK * N_DIM;
    }

    #pragma unroll
    for (int i = 0; i < TM; i++) {
        const int m = block_m + ty * TM + i;
        const float xs = g_xsq[m];
        #pragma unroll
        for (int j = 0; j < TN; j += 4) {
            const int n = block_n + tx * TN + j;
            float4 r;
            r.x = expf(-gamma * (xs + g_musq[n + 0] - 2.f * acc[i][j + 0]));
            r.y = expf(-gamma * (xs + g_musq[n + 1] - 2.f * acc[i][j + 1]));
            r.z = expf(-gamma * (xs + g_musq[n + 2] - 2.f * acc[i][j + 2]));
            r.w = expf(-gamma * (xs + g_musq[n + 3] - 2.f * acc[i][j + 3]));
            *(float4*)&out[(size_t)m * N_DIM + n] = r;
        }
    }
}

// ---------------------------------------------------------------------------
// Launch: inputs per metadata order: x (B*K f32), mu (K*U f32), gamma (1 f32)
// Guard-slot init must happen before prep's atomics -> tiny memset via kernel?
// No: init is folded into a 1-block prologue? Simplest correct scheme: memset
// the slots with cudaMemsetAsync (graph-capturable, no allocation).
// ---------------------------------------------------------------------------
extern "C" void kernel_launch(void* const* d_in, const int* in_sizes, int n_in,
                              void* d_out, int out_size) {
    const float* x     = (const float*)d_in[0];
    const float* mu    = (const float*)d_in[1];
    const float* gamma = (const float*)d_in[2];
    float* out = (float*)d_out;

    // init guard slots: xmin=+inf (0x7F800000), mumax=0
    void* xmin_p = nullptr; void* mumax_p = nullptr;
    cudaGetSymbolAddress(&xmin_p, g_xmin_tile);
    cudaGetSymbolAddress(&mumax_p, g_mumax_tile);
    // 0x7F7F7F7F > any finite norm bits we care about? Not +inf, but
    // 0x7F7F7F7F = 3.39e38f which safely exceeds any ||x||^2 here; byte memset
    // is the only pattern cudaMemsetAsync supports.
    cudaMemsetAsync(xmin_p, 0x7F, MTILES * sizeof(unsigned int));
    cudaMemsetAsync(mumax_p, 0x00, NTILES * sizeof(unsigned int));

    prep_kernel<<<PREP_BLOCKS, 256>>>(x, mu, (float4*)out);

    dim3 grid(NTILES, MTILES);
    rbf_guarded_kernel<<<grid, 256>>>(x, mu, gamma, out);
}

// round 6
// speedup vs baseline: 40.5492x; 1.0624x over previous
#include <cuda_runtime.h>
#include <math.h>

// Problem dims (fixed by the dataset): x (B, K), mu (K, U), out (B, U)
#define B_DIM 8192
#define K_DIM 1024
#define N_DIM 4096

// GEMM tiling (fallback path)
#define BM 128
#define BN 128
#define BK 16
#define TM 8
#define TN 8
#define APAD 4

#define MTILES (B_DIM / BM)   // 64
#define NTILES (N_DIM / BN)   // 32
#define NT_PER_CTA 8          // N-tiles handled per guard CTA
#define GUARD_BLOCKS (MTILES * (NTILES / NT_PER_CTA))   // 256

// Underflow threshold: exp(-t) with t > ~104 rounds to 0 in fp32
#define UNDERFLOW_T 118.0f

// Scratch (no allocations allowed -> device globals)
__device__ float g_xsq[B_DIM];
__device__ float g_musq[N_DIM];
// Guard slots, single array so ONE memset(0xFF) initializes everything:
//   [0, MTILES):             min ||x||^2 per row-tile, raw bits, atomicMin
//   [MTILES, MTILES+NTILES): max ||mu||^2 per col-tile, COMPLEMENT bits,
//                            atomicMin(~bits) == complement of max(bits)
__device__ unsigned int g_guard[MTILES + NTILES];

// ---------------------------------------------------------------------------
// Fused prep kernel: norms (reads) + zero-fill (writes) in one launch so both
// DRAM directions are busy simultaneously. This launch is at the combined
// DRAM-traffic floor (~184 MB), do not expect it below ~28 us.
// ---------------------------------------------------------------------------
#define XSQ_BLOCKS (B_DIM / 8)            // 1024
#define MUSQ_BLOCKS (N_DIM / 8)           // 512
#define FILL_BLOCKS 2048
#define PREP_BLOCKS (XSQ_BLOCKS + MUSQ_BLOCKS + FILL_BLOCKS)

__global__ __launch_bounds__(256) void prep_kernel(
    const float* __restrict__ x, const float* __restrict__ mu,
    float4* __restrict__ out)
{
    const int tid = threadIdx.x;
    if (blockIdx.x < XSQ_BLOCKS) {
        // ---- xsq: warp w handles row blockIdx*8 + w
        const int warp = tid >> 5, lane = tid & 31;
        const int row = blockIdx.x * 8 + warp;
        const float4* xr = (const float4*)(x + (size_t)row * K_DIM);
        float s = 0.f;
        #pragma unroll
        for (int i = 0; i < 8; i++) {
            float4 v = xr[lane + 32 * i];
            s += v.x * v.x + v.y * v.y + v.z * v.z + v.w * v.w;
        }
        #pragma unroll
        for (int o = 16; o > 0; o >>= 1) s += __shfl_xor_sync(0xffffffffu, s, o);
        if (lane == 0) {
            g_xsq[row] = s;
            atomicMin(&g_guard[row >> 7], __float_as_uint(s));
        }
    } else if (blockIdx.x < XSQ_BLOCKS + MUSQ_BLOCKS) {
        // ---- musq: CTA covers 8 columns; 32 K-slices of 32 rows each
        const int cb = (blockIdx.x - XSQ_BLOCKS) * 8;
        const int col = cb + (tid & 7);
        const int ks = tid >> 3;               // 0..31
        const float* p = mu + (size_t)(ks * 32) * N_DIM + col;
        float s = 0.f;
        #pragma unroll 8
        for (int i = 0; i < 32; i++) {
            float v = p[(size_t)i * N_DIM];
            s += v * v;
        }
        __shared__ float sm[32][8];
        sm[ks][tid & 7] = s;
        __syncthreads();
        if (tid < 8) {
            float t = 0.f;
            #pragma unroll
            for (int k = 0; k < 32; k++) t += sm[k][tid];
            g_musq[cb + tid] = t;
            // max via complemented atomicMin (bits monotonic for non-neg floats)
            atomicMin(&g_guard[MTILES + ((cb + tid) >> 7)], ~__float_as_uint(t));
        }
    } else {
        // ---- fill: streaming zero stores, 16 float4 per thread
        const int fb = blockIdx.x - (XSQ_BLOCKS + MUSQ_BLOCKS);
        const float4 z = make_float4(0.f, 0.f, 0.f, 0.f);
        const size_t total = (size_t)B_DIM * N_DIM / 4;       // 8M float4
        const size_t stride = (size_t)FILL_BLOCKS * 256;
        for (size_t i = (size_t)fb * 256 + tid; i < total; i += stride)
            __stcs(&out[i], z);
    }
}

// ---------------------------------------------------------------------------
// Guarded GEMM kernel: 256 CTAs, each owns one 128-row tile x 8 col-tiles.
// Per tile: bound = (sqrt(min||x||^2) - sqrt(max||mu||^2))^2. If
// gamma*bound > 118 every exp() underflows to fp32 zero and prep already
// zeroed it -> skip. Otherwise compute the exact fp32 GEMM + RBF epilogue.
// Taken path on this dataset: all tiles skip -> one launch wave of trivial
// CTAs (~2us).
// ---------------------------------------------------------------------------
__global__ __launch_bounds__(256) void rbf_guarded_kernel(
    const float* __restrict__ x,
    const float* __restrict__ mu,
    const float* __restrict__ gamma_p,
    float* __restrict__ out)
{
    const int tid = threadIdx.x;
    const int mt = blockIdx.x >> 2;                 // 0..63
    const int nt0 = (blockIdx.x & 3) * NT_PER_CTA;  // 0,8,16,24
    const int block_m = mt * BM;
    const float gamma = *gamma_p;

    const float rx = sqrtf(fmaxf(__uint_as_float(g_guard[mt]), 0.f));

    __shared__ float As[BK][BM + APAD];
    __shared__ float Bs[BK][BN];

    for (int nt = nt0; nt < nt0 + NT_PER_CTA; nt++) {
        const float mx_mu = __uint_as_float(~g_guard[MTILES + nt]);
        const float d = rx - sqrtf(fmaxf(mx_mu, 0.f));
        if (gamma > 0.f && d > 0.f && gamma * d * d > UNDERFLOW_T)
            continue;   // tile provably all-zero; prep already wrote it

        // ---------------- fallback: exact fp32 GEMM + RBF ----------------
        const int block_n = nt * BN;
        const int aRow = tid >> 2;
        const int aCol = (tid & 3) * 4;
        const int bRow = tid >> 5;
        const int bCol = (tid & 31) * 4;
        const int ty = tid >> 4;
        const int tx = tid & 15;

        const float* xg = x + (size_t)(block_m + aRow) * K_DIM + aCol;
        const float* bg = mu + (size_t)bRow * N_DIM + block_n + bCol;

        float acc[TM][TN];
        #pragma unroll
        for (int i = 0; i < TM; i++)
            #pragma unroll
            for (int j = 0; j < TN; j++) acc[i][j] = 0.f;

        __syncthreads();   // smem may be in use from a previous iteration

        for (int k0 = 0; k0 < K_DIM; k0 += BK) {
            float4 a0 = *(const float4*)(xg);
            float4 a1 = *(const float4*)(xg + (size_t)64 * K_DIM);
            As[aCol + 0][aRow] = a0.x;
            As[aCol + 1][aRow] = a0.y;
            As[aCol + 2][aRow] = a0.z;
            As[aCol + 3][aRow] = a0.w;
            As[aCol + 0][aRow + 64] = a1.x;
            As[aCol + 1][aRow + 64] = a1.y;
            As[aCol + 2][aRow + 64] = a1.z;
            As[aCol + 3][aRow + 64] = a1.w;

            float4 b0 = *(const float4*)(bg);
            float4 b1 = *(const float4*)(bg + (size_t)8 * N_DIM);
            *(float4*)&Bs[bRow][bCol]     = b0;
            *(float4*)&Bs[bRow + 8][bCol] = b1;

            __syncthreads();

            #pragma unroll
            for (int k = 0; k < BK; k++) {
                float a_frag[TM], b_frag[TN];
                #pragma unroll
                for (int i = 0; i < TM; i += 4)
                    *(float4*)&a_frag[i] = *(const float4*)&As[k][ty * TM + i];
                #pragma unroll
                for (int j = 0; j < TN; j += 4)
                    *(float4*)&b_frag[j] = *(const float4*)&Bs[k][tx * TN + j];
                #pragma unroll
                for (int i = 0; i < TM; i++)
                    #pragma unroll
                    for (int j = 0; j < TN; j++)
                        acc[i][j] = fmaf(a_frag[i], b_frag[j], acc[i][j]);
            }

            __syncthreads();
            xg += BK;
            bg += (size_t)BK * N_DIM;
        }

        #pragma unroll
        for (int i = 0; i < TM; i++) {
            const int m = block_m + ty * TM + i;
            const float xs = g_xsq[m];
            #pragma unroll
            for (int j = 0; j < TN; j += 4) {
                const int n = block_n + tx * TN + j;
                float4 r;
                r.x = expf(-gamma * (xs + g_musq[n + 0] - 2.f * acc[i][j + 0]));
                r.y = expf(-gamma * (xs + g_musq[n + 1] - 2.f * acc[i][j + 1]));
                r.z = expf(-gamma * (xs + g_musq[n + 2] - 2.f * acc[i][j + 2]));
                r.w = expf(-gamma * (xs + g_musq[n + 3] - 2.f * acc[i][j + 3]));
                *(float4*)&out[(size_t)m * N_DIM + n] = r;
            }
        }
    }
}

// ---------------------------------------------------------------------------
// Launch: inputs per metadata order: x (B*K f32), mu (K*U f32), gamma (1 f32)
// ---------------------------------------------------------------------------
extern "C" void kernel_launch(void* const* d_in, const int* in_sizes, int n_in,
                              void* d_out, int out_size) {
    const float* x     = (const float*)d_in[0];
    const float* mu    = (const float*)d_in[1];
    const float* gamma = (const float*)d_in[2];
    float* out = (float*)d_out;

    // Single memset: 0xFF bytes = 0xFFFFFFFF per slot.
    //   xmin slots: max-uint is a valid atomicMin identity.
    //   mumax slots: stored complemented, so 0xFFFFFFFF == complement of 0.
    void* guard_p = nullptr;
    cudaGetSymbolAddress(&guard_p, g_guard);
    cudaMemsetAsync(guard_p, 0xFF, (MTILES + NTILES) * sizeof(unsigned int));

    prep_kernel<<<PREP_BLOCKS, 256>>>(x, mu, (float4*)out);

    rbf_guarded_kernel<<<GUARD_BLOCKS, 256>>>(x, mu, gamma, out);
}

// round 7
// speedup vs baseline: 41.7980x; 1.0308x over previous
#include <cuda_runtime.h>
#include <math.h>

// Problem dims (fixed by the dataset): x (B, K), mu (K, U), out (B, U)
#define B_DIM 8192
#define K_DIM 1024
#define N_DIM 4096

// GEMM tiling (fallback path; never taken on this dataset)
#define BM 128
#define BN 128
#define BK 16
#define TM 8
#define TN 8
#define APAD 4

#define MTILES (B_DIM / BM)   // 64
#define NTILES (N_DIM / BN)   // 32
#define NT_PER_CTA 8
#define GUARD_BLOCKS (MTILES * (NTILES / NT_PER_CTA))   // 256

// Underflow threshold: exp(-t) with t > ~104 rounds to 0 in fp32
#define UNDERFLOW_T 118.0f

// Grid layout of the single fused kernel
#define XSQ_BLOCKS  (B_DIM / 8)           // 1024
#define MUSQ_BLOCKS (N_DIM / 8)           // 512
#define FILL_BLOCKS 2048
#define PROD_BLOCKS (XSQ_BLOCKS + MUSQ_BLOCKS + FILL_BLOCKS)  // 3584
#define GRID_BLOCKS (PROD_BLOCKS + GUARD_BLOCKS)              // 3840

// Scratch (no allocations allowed -> device globals)
__device__ float g_xsq[B_DIM];
__device__ float g_musq[N_DIM];
__device__ unsigned int g_done = 0;        // producer completion counter
__device__ unsigned int g_guard_done = 0;  // guard-CTA completion counter

// ---------------------------------------------------------------------------
// Single fused kernel.
//   bids [0,1024):      xsq  — one warp per x row
//   bids [1024,1536):   musq — 8 cols x 32 K-slices per CTA
//   bids [1536,3584):   fill — streaming zero stores (valid for skipped tiles)
//   bids [3584,3840):   guard+GEMM — spin until all producers done, then per
//                       128x128 tile: bound = (min||x|| - max||mu||)^2; if
//                       gamma*bound > 118 every exp underflows to fp32 zero
//                       (already written by fill) -> skip; else exact fp32
//                       GEMM + RBF epilogue (always correct).
// Deadlock-free ordering: guard CTAs have the highest blockIdx, so every
// producer CTA is scheduled before any guard CTA occupies a slot; producers
// never wait; 256 spinners << concurrent-CTA capacity.
// Counters self-reset by the last guard CTA -> safe under graph replay.
// ---------------------------------------------------------------------------
__global__ __launch_bounds__(256, 6) void fused_rbf_kernel(
    const float* __restrict__ x, const float* __restrict__ mu,
    const float* __restrict__ gamma_p, float* __restrict__ out)
{
    const int tid = threadIdx.x;
    const unsigned bid = blockIdx.x;

    if (bid < PROD_BLOCKS) {
        if (bid < XSQ_BLOCKS) {
            // ---- xsq: warp w handles row bid*8 + w
            const int warp = tid >> 5, lane = tid & 31;
            const int row = bid * 8 + warp;
            const float4* xr = (const float4*)(x + (size_t)row * K_DIM);
            float s = 0.f;
            #pragma unroll
            for (int i = 0; i < 8; i++) {
                float4 v = xr[lane + 32 * i];
                s += v.x * v.x + v.y * v.y + v.z * v.z + v.w * v.w;
            }
            #pragma unroll
            for (int o = 16; o > 0; o >>= 1) s += __shfl_xor_sync(0xffffffffu, s, o);
            if (lane == 0) g_xsq[row] = s;
        } else if (bid < XSQ_BLOCKS + MUSQ_BLOCKS) {
            // ---- musq: CTA covers 8 columns; 32 K-slices of 32 rows each
            const int cb = (bid - XSQ_BLOCKS) * 8;
            const int col = cb + (tid & 7);
            const int ks = tid >> 3;               // 0..31
            const float* p = mu + (size_t)(ks * 32) * N_DIM + col;
            float s = 0.f;
            #pragma unroll 8
            for (int i = 0; i < 32; i++) {
                float v = p[(size_t)i * N_DIM];
                s += v * v;
            }
            __shared__ float sm[32][8];
            sm[ks][tid & 7] = s;
            __syncthreads();
            if (tid < 8) {
                float t = 0.f;
                #pragma unroll
                for (int k = 0; k < 32; k++) t += sm[k][tid];
                g_musq[cb + tid] = t;
            }
        } else {
            // ---- fill: streaming zero stores
            const int fb = bid - (XSQ_BLOCKS + MUSQ_BLOCKS);
            float4* o4 = (float4*)out;
            const float4 z = make_float4(0.f, 0.f, 0.f, 0.f);
            const size_t total = (size_t)B_DIM * N_DIM / 4;   // 8M float4
            const size_t stride = (size_t)FILL_BLOCKS * 256;
            for (size_t i = (size_t)fb * 256 + tid; i < total; i += stride)
                __stcs(&o4[i], z);
        }
        // ---- producer completion: release writes, bump counter
        __threadfence();
        __syncthreads();
        if (tid == 0) atomicAdd(&g_done, 1u);
        return;
    }

    // ======================= guard + fallback GEMM =======================
    const int g = bid - PROD_BLOCKS;                // 0..255
    const int mt = g >> 2;                          // 0..63
    const int nt0 = (g & 3) * NT_PER_CTA;           // 0,8,16,24
    const int block_m = mt * BM;

    // wait for all producers
    if (tid == 0) {
        volatile unsigned int* p = &g_done;
        while (*p < PROD_BLOCKS) __nanosleep(64);
        __threadfence();
    }
    __syncthreads();

    const float gamma = *gamma_p;

    // local tile reductions: rx = min xsq over 128 rows; per-nt max musq
    __shared__ float red_min[8];
    __shared__ float red_max[8];
    {
        const int warp = tid >> 5, lane = tid & 31;
        float v = (tid < 128) ? g_xsq[block_m + tid] : __int_as_float(0x7f800000);
        #pragma unroll
        for (int o = 16; o > 0; o >>= 1)
            v = fminf(v, __shfl_xor_sync(0xffffffffu, v, o));
        if (lane == 0) red_min[warp] = v;

        // warp w covers N-tile nt0 + w (128 musq values, 4 per lane)
        float mx = 0.f;
        const int base = (nt0 + warp) * BN;
        #pragma unroll
        for (int k = 0; k < 4; k++)
            mx = fmaxf(mx, g_musq[base + 32 * k + lane]);
        #pragma unroll
        for (int o = 16; o > 0; o >>= 1)
            mx = fmaxf(mx, __shfl_xor_sync(0xffffffffu, mx, o));
        if (lane == 0) red_max[warp] = mx;
        __syncthreads();
    }
    float rxmin = red_min[0];
    #pragma unroll
    for (int w = 1; w < 8; w++) rxmin = fminf(rxmin, red_min[w]);
    const float rxs = sqrtf(fmaxf(rxmin, 0.f));

    __shared__ float As[BK][BM + APAD];
    __shared__ float Bs[BK][BN];

    for (int j = 0; j < NT_PER_CTA; j++) {
        const float d = rxs - sqrtf(fmaxf(red_max[j], 0.f));
        if (gamma > 0.f && d > 0.f && gamma * d * d > UNDERFLOW_T)
            continue;   // tile provably all-zero; fill already wrote it

        // ---------------- fallback: exact fp32 GEMM + RBF ----------------
        const int block_n = (nt0 + j) * BN;
        const int aRow = tid >> 2;
        const int aCol = (tid & 3) * 4;
        const int bRow = tid >> 5;
        const int bCol = (tid & 31) * 4;
        const int ty = tid >> 4;
        const int tx = tid & 15;

        const float* xg = x + (size_t)(block_m + aRow) * K_DIM + aCol;
        const float* bg = mu + (size_t)bRow * N_DIM + block_n + bCol;

        float acc[TM][TN];
        #pragma unroll
        for (int i = 0; i < TM; i++)
            #pragma unroll
            for (int jj = 0; jj < TN; jj++) acc[i][jj] = 0.f;

        __syncthreads();   // smem may be in use from a previous iteration

        for (int k0 = 0; k0 < K_DIM; k0 += BK) {
            float4 a0 = *(const float4*)(xg);
            float4 a1 = *(const float4*)(xg + (size_t)64 * K_DIM);
            As[aCol + 0][aRow] = a0.x;
            As[aCol + 1][aRow] = a0.y;
            As[aCol + 2][aRow] = a0.z;
            As[aCol + 3][aRow] = a0.w;
            As[aCol + 0][aRow + 64] = a1.x;
            As[aCol + 1][aRow + 64] = a1.y;
            As[aCol + 2][aRow + 64] = a1.z;
            As[aCol + 3][aRow + 64] = a1.w;

            float4 b0 = *(const float4*)(bg);
            float4 b1 = *(const float4*)(bg + (size_t)8 * N_DIM);
            *(float4*)&Bs[bRow][bCol]     = b0;
            *(float4*)&Bs[bRow + 8][bCol] = b1;

            __syncthreads();

            #pragma unroll
            for (int k = 0; k < BK; k++) {
                float a_frag[TM], b_frag[TN];
                #pragma unroll
                for (int i = 0; i < TM; i += 4)
                    *(float4*)&a_frag[i] = *(const float4*)&As[k][ty * TM + i];
                #pragma unroll
                for (int jj = 0; jj < TN; jj += 4)
                    *(float4*)&b_frag[jj] = *(const float4*)&Bs[k][tx * TN + jj];
                #pragma unroll
                for (int i = 0; i < TM; i++)
                    #pragma unroll
                    for (int jj = 0; jj < TN; jj++)
                        acc[i][jj] = fmaf(a_frag[i], b_frag[jj], acc[i][jj]);
            }

            __syncthreads();
            xg += BK;
            bg += (size_t)BK * N_DIM;
        }

        #pragma unroll
        for (int i = 0; i < TM; i++) {
            const int m = block_m + ty * TM + i;
            const float xs = g_xsq[m];
            #pragma unroll
            for (int jj = 0; jj < TN; jj += 4) {
                const int n = block_n + tx * TN + jj;
                float4 r;
                r.x = expf(-gamma * (xs + g_musq[n + 0] - 2.f * acc[i][jj + 0]));
                r.y = expf(-gamma * (xs + g_musq[n + 1] - 2.f * acc[i][jj + 1]));
                r.z = expf(-gamma * (xs + g_musq[n + 2] - 2.f * acc[i][jj + 2]));
                r.w = expf(-gamma * (xs + g_musq[n + 3] - 2.f * acc[i][jj + 3]));
                *(float4*)&out[(size_t)m * N_DIM + n] = r;
            }
        }
    }

    // ---- counter self-reset so the next graph replay starts clean
    __syncthreads();
    if (tid == 0) {
        __threadfence();
        if (atomicAdd(&g_guard_done, 1u) == GUARD_BLOCKS - 1) {
            atomicExch(&g_done, 0u);
            atomicExch(&g_guard_done, 0u);
        }
    }
}

// ---------------------------------------------------------------------------
// Launch: inputs per metadata order: x (B*K f32), mu (K*U f32), gamma (1 f32)
// ---------------------------------------------------------------------------
extern "C" void kernel_launch(void* const* d_in, const int* in_sizes, int n_in,
                              void* d_out, int out_size) {
    const float* x     = (const float*)d_in[0];
    const float* mu    = (const float*)d_in[1];
    const float* gamma = (const float*)d_in[2];
    float* out = (float*)d_out;

    fused_rbf_kernel<<<GRID_BLOCKS, 256>>>(x, mu, gamma, out);
}